// round 15
// baseline (speedup 1.0000x reference)
#include <cuda_runtime.h>
#include <cuda_bf16.h>
#include <math.h>
#include <stdint.h>

#define D_MODEL 1024
#define SEQ     2048
#define BATCH   4
#define NTOK    (BATCH*SEQ)      // 8192
#define NHEAD   16
#define HDIM    64
#define DFF     4096

// ---------------- scratch (alloc-free: __device__ globals) ----------------
__device__ __nv_bfloat16 g_qkv [(size_t)NTOK * 3 * D_MODEL];   // 48 MB bf16
__device__ float         g_x1  [(size_t)NTOK * D_MODEL];       // 32 MB fp32
__device__ __nv_bfloat16 g_nrm [(size_t)NTOK * D_MODEL];       // 16 MB
__device__ __nv_bfloat16 g_attn[(size_t)NTOK * D_MODEL];       // 16 MB
__device__ __nv_bfloat16 g_h   [(size_t)NTOK * DFF];           // 64 MB
__device__ __nv_bfloat16 g_wq  [(size_t)3 * D_MODEL * D_MODEL];
__device__ __nv_bfloat16 g_wo  [(size_t)D_MODEL * D_MODEL];
__device__ __nv_bfloat16 g_w1  [(size_t)D_MODEL * DFF];
__device__ __nv_bfloat16 g_w2  [(size_t)DFF * D_MODEL];

// ---------------- helpers ----------------
__device__ __forceinline__ float gelu_exact(float x) {
    return 0.5f * x * (1.0f + erff(x * 0.70710678118654752f));
}
__device__ __forceinline__ uint2 f4_to_bf16x4(float4 v) {
    __nv_bfloat162 lo = __floats2bfloat162_rn(v.x, v.y);
    __nv_bfloat162 hi = __floats2bfloat162_rn(v.z, v.w);
    uint2 r;
    r.x = *(uint32_t*)&lo;
    r.y = *(uint32_t*)&hi;
    return r;
}
__device__ __forceinline__ uint32_t f2_to_bf16x2(float a, float b) {
    __nv_bfloat162 p = __floats2bfloat162_rn(a, b);
    return *(uint32_t*)&p;
}
__device__ __forceinline__ void ldsm_x4(uint32_t& r0, uint32_t& r1,
                                        uint32_t& r2, uint32_t& r3,
                                        const void* p) {
    uint32_t a = (uint32_t)__cvta_generic_to_shared(p);
    asm volatile("ldmatrix.sync.aligned.m8n8.x4.shared.b16 {%0,%1,%2,%3}, [%4];"
                 : "=r"(r0), "=r"(r1), "=r"(r2), "=r"(r3) : "r"(a));
}
__device__ __forceinline__ void ldsm_x4_t(uint32_t& r0, uint32_t& r1,
                                          uint32_t& r2, uint32_t& r3,
                                          const void* p) {
    uint32_t a = (uint32_t)__cvta_generic_to_shared(p);
    asm volatile("ldmatrix.sync.aligned.m8n8.x4.trans.shared.b16 {%0,%1,%2,%3}, [%4];"
                 : "=r"(r0), "=r"(r1), "=r"(r2), "=r"(r3) : "r"(a));
}
__device__ __forceinline__ void cp16(void* dst, const void* src) {
    uint32_t d = (uint32_t)__cvta_generic_to_shared(dst);
    asm volatile("cp.async.cg.shared.global [%0], [%1], 16;" :: "r"(d), "l"(src));
}
#define MMA_BF16(accv, afv, bfv)                                            \
    asm volatile(                                                           \
        "mma.sync.aligned.m16n8k16.row.col.f32.bf16.bf16.f32 "              \
        "{%0,%1,%2,%3}, {%4,%5,%6,%7}, {%8,%9}, {%0,%1,%2,%3};"             \
        : "+f"((accv)[0]), "+f"((accv)[1]), "+f"((accv)[2]), "+f"((accv)[3])\
        : "r"((afv)[0]), "r"((afv)[1]), "r"((afv)[2]), "r"((afv)[3]),       \
          "r"((bfv)[0]), "r"((bfv)[1]))

// Q pre-scale folds 1/sqrt(64) AND log2(e): softmax computed base-2.
#define QSCALE (0.125f * 1.44269504088896340736f)

// ---------------- LayerNorm core: warp-per-token, shuffle-only --------------
__device__ __forceinline__ void ln_token(
    const float* __restrict__ x, const float* __restrict__ g,
    const float* __restrict__ b, __nv_bfloat16* __restrict__ y,
    int tok, int lane)
{
    const float4* row = (const float4*)(x + (size_t)tok * D_MODEL);
    float4 v[8];
    float s = 0.f, sq = 0.f;
    #pragma unroll
    for (int p = 0; p < 8; p++) {
        v[p] = row[p * 32 + lane];
        s  += v[p].x + v[p].y + v[p].z + v[p].w;
        sq += v[p].x*v[p].x + v[p].y*v[p].y + v[p].z*v[p].z + v[p].w*v[p].w;
    }
    #pragma unroll
    for (int o = 16; o > 0; o >>= 1) {
        s  += __shfl_xor_sync(0xffffffffu, s,  o);
        sq += __shfl_xor_sync(0xffffffffu, sq, o);
    }
    float mean = s * (1.0f / D_MODEL);
    float var  = sq * (1.0f / D_MODEL) - mean * mean;
    float rstd = rsqrtf(var + 1e-5f);
    uint2* yo = (uint2*)(y + (size_t)tok * D_MODEL);
    #pragma unroll
    for (int p = 0; p < 8; p++) {
        float4 gg = ((const float4*)g)[p * 32 + lane];
        float4 bb = ((const float4*)b)[p * 32 + lane];
        float4 o4;
        o4.x = (v[p].x - mean) * rstd * gg.x + bb.x;
        o4.y = (v[p].y - mean) * rstd * gg.y + bb.y;
        o4.z = (v[p].z - mean) * rstd * gg.z + bb.z;
        o4.w = (v[p].w - mean) * rstd * gg.w + bb.w;
        yo[p * 32 + lane] = f4_to_bf16x4(o4);
    }
}

// LN standalone (LN2): 8 tokens per block, 1024 blocks.
__global__ void __launch_bounds__(256) ln_kernel(
    const float* __restrict__ x, const float* __restrict__ g,
    const float* __restrict__ b, __nv_bfloat16* __restrict__ y)
{
    int tok = blockIdx.x * 8 + (threadIdx.x >> 5);
    ln_token(x, g, b, y, tok, threadIdx.x & 31);
}

// LN1 fused with weight convert: blocks [0, NTOK/8) do LN1,
// blocks [NTOK/8, ...) do segmented fp32->bf16 weight conversion.
#define LN_BLOCKS (NTOK / 8)
__global__ void __launch_bounds__(256) ln1_cvt_kernel(
    const float* __restrict__ x, const float* __restrict__ g,
    const float* __restrict__ b, __nv_bfloat16* __restrict__ y,
    const float4* __restrict__ s0, uint2* __restrict__ d0, int n0e,
    const float4* __restrict__ s1, uint2* __restrict__ d1, int n1e,
    const float4* __restrict__ s2, uint2* __restrict__ d2, int n2e,
    const float4* __restrict__ s3, uint2* __restrict__ d3, int n3e)
{
    if (blockIdx.x < LN_BLOCKS) {
        int tok = blockIdx.x * 8 + (threadIdx.x >> 5);
        ln_token(x, g, b, y, tok, threadIdx.x & 31);
        return;
    }
    int i = (blockIdx.x - LN_BLOCKS) * 256 + threadIdx.x;
    const float4* src; uint2* dst; int n;
    if (i < n0e)                      { src = s0; dst = d0; n = i; }
    else if ((i -= n0e) < n1e)        { src = s1; dst = d1; n = i; }
    else if ((i -= n1e) < n2e)        { src = s2; dst = d2; n = i; }
    else if ((i -= n2e) < n3e)        { src = s3; dst = d3; n = i; }
    else return;
    dst[n] = f4_to_bf16x4(src[n]);
}

// ---------------- bf16 GEMM: EXACT R6 configuration --------------------------
// BK=32, 3-stage cp.async, wait_group 1, refill AFTER compute.
// EPI: 0 bias, 1 bias+gelu, 2 bias+residual, 3 bias + qscale (cols<1024)
#define ASTR 40
#define BSTR 136
#define GSTAGE 3
#define GEMM_SMEM (GSTAGE * (128 * ASTR + 32 * BSTR) * 2)   // 56832 B

template<int EPI, int OUTBF>
__global__ void __launch_bounds__(256, 2) gemm_bf16(
    const __nv_bfloat16* __restrict__ A, const __nv_bfloat16* __restrict__ B,
    const float* __restrict__ bias, const float* __restrict__ Rsd,
    void* __restrict__ Cout, int M, int N, int K)
{
    extern __shared__ __nv_bfloat16 dynsm[];
    __nv_bfloat16* Asm = dynsm;
    __nv_bfloat16* Bsm = dynsm + GSTAGE * 128 * ASTR;

    const int tid  = threadIdx.x;
    const int lane = tid & 31, warp = tid >> 5;
    const int wm = warp >> 2, wn = warp & 3;
    const int g  = lane >> 2, t4 = lane & 3;
    const int l15 = lane & 15, lhi = (lane >> 4) << 3;
    const int m0 = blockIdx.y * 128, n0 = blockIdx.x * 128;

    float acc[4][4][4];
    #pragma unroll
    for (int i = 0; i < 4; i++)
        #pragma unroll
        for (int j = 0; j < 4; j++)
            #pragma unroll
            for (int r = 0; r < 4; r++) acc[i][j][r] = 0.f;

    const int ar = tid >> 2,  ac8 = (tid & 3) * 8;
    const int br = tid >> 4,  bc8 = (tid & 15) * 8;
    const __nv_bfloat16* Abase = A + (size_t)(m0 + ar) * K + ac8;
    const __nv_bfloat16* Bbase = B + n0 + bc8;

    auto load_stage = [&](int s, int k0) {
        __nv_bfloat16* as = Asm + s * 128 * ASTR;
        __nv_bfloat16* bs = Bsm + s * 32 * BSTR;
        cp16(&as[(ar     ) * ASTR + ac8], Abase + k0);
        cp16(&as[(ar + 64) * ASTR + ac8], Abase + (size_t)64 * K + k0);
        cp16(&bs[(br     ) * BSTR + bc8], Bbase + (size_t)(k0 + br) * N);
        cp16(&bs[(br + 16) * BSTR + bc8], Bbase + (size_t)(k0 + br + 16) * N);
    };

    load_stage(0, 0);
    asm volatile("cp.async.commit_group;");
    load_stage(1, 32);
    asm volatile("cp.async.commit_group;");

    int buf = 0;
    for (int k0 = 0; k0 < K; k0 += 32) {
        asm volatile("cp.async.wait_group 1;");
        __syncthreads();

        const __nv_bfloat16* a  = Asm + buf * 128 * ASTR;
        const __nv_bfloat16* bs = Bsm + buf * 32 * BSTR;
        #pragma unroll
        for (int ks = 0; ks < 2; ks++) {
            const int kb = ks * 16;
            uint32_t af[4][4];
            #pragma unroll
            for (int mt = 0; mt < 4; mt++)
                ldsm_x4(af[mt][0], af[mt][1], af[mt][2], af[mt][3],
                        &a[(wm * 64 + mt * 16 + l15) * ASTR + kb + lhi]);
            uint32_t bf_[4][2];
            #pragma unroll
            for (int ntp = 0; ntp < 2; ntp++) {
                uint32_t r0, r1, r2, r3;
                ldsm_x4_t(r0, r1, r2, r3,
                          &bs[(kb + l15) * BSTR + wn * 32 + ntp * 16 + lhi]);
                bf_[2 * ntp][0] = r0;     bf_[2 * ntp][1] = r1;
                bf_[2 * ntp + 1][0] = r2; bf_[2 * ntp + 1][1] = r3;
            }
            #pragma unroll
            for (int mt = 0; mt < 4; mt++)
                #pragma unroll
                for (int nt = 0; nt < 4; nt++)
                    MMA_BF16(acc[mt][nt], af[mt], bf_[nt]);
        }

        if (k0 + 64 < K) {
            int s = buf + 2; if (s >= GSTAGE) s -= GSTAGE;
            load_stage(s, k0 + 64);
        }
        asm volatile("cp.async.commit_group;");
        buf = (buf + 1 == GSTAGE) ? 0 : buf + 1;
    }

    #pragma unroll
    for (int mt = 0; mt < 4; mt++) {
        #pragma unroll
        for (int nt = 0; nt < 4; nt++) {
            int row = m0 + wm * 64 + mt * 16 + g;
            int col = n0 + wn * 32 + nt * 8 + t4 * 2;
            float2 bb = *(const float2*)(bias + col);
            #pragma unroll
            for (int h = 0; h < 2; h++) {
                int r = row + h * 8;
                float2 v;
                v.x = acc[mt][nt][h * 2 + 0] + bb.x;
                v.y = acc[mt][nt][h * 2 + 1] + bb.y;
                if (EPI == 1) { v.x = gelu_exact(v.x); v.y = gelu_exact(v.y); }
                if (EPI == 2) {
                    float2 rr = *(const float2*)(Rsd + (size_t)r * N + col);
                    v.x += rr.x; v.y += rr.y;
                }
                if (EPI == 3 && col < 1024) { v.x *= QSCALE; v.y *= QSCALE; }
                if (OUTBF) {
                    __nv_bfloat16* C = (__nv_bfloat16*)Cout;
                    *(uint32_t*)&C[(size_t)r * N + col] = f2_to_bf16x2(v.x, v.y);
                } else {
                    float* C = (float*)Cout;
                    *(float2*)(C + (size_t)r * N + col) = v;
                }
            }
        }
    }
}

// ---------------- Flash attention v4: register-resident P (R14) -------------
#define FQ   128
#define FK   64
#define FST  72
#define STG_KV (FK * FST)
#define FLASH_SMEM ((FQ * FST + 4 * STG_KV) * 2)   // 55296 B

__global__ void __launch_bounds__(256, 2) flash_tc(
    const __nv_bfloat16* __restrict__ qkv, __nv_bfloat16* __restrict__ outp)
{
    extern __shared__ __nv_bfloat16 smb[];
    __nv_bfloat16* Qs = smb;                    // Q staging [128][FST]
    __nv_bfloat16* Ks = smb + FQ * FST;         // 2 x [64][FST]
    __nv_bfloat16* Vs = Ks + 2 * STG_KV;        // 2 x [64][FST]

    const int tid  = threadIdx.x;
    const int lane = tid & 31, w = tid >> 5;
    const int g = lane >> 2, t4 = lane & 3;
    const int l15 = lane & 15, l7 = lane & 7;
    const int lhi = (lane >> 4) << 3, selk = (lane >> 3) & 1;
    const int qt = (SEQ / FQ - 1) - blockIdx.x;   // heavy tiles first
    const int h  = blockIdx.y, b = blockIdx.z;
    const int tok0 = b * SEQ + qt * FQ;
    const int mrow = w * 16 + g;
    const int nkt = 2 * qt + 2;

    auto load_kv = [&](int stage, int kt2) {
        const __nv_bfloat16* kb_ =
            qkv + (size_t)(b * SEQ + kt2 * FK) * 3072 + 1024 + h * 64;
        const __nv_bfloat16* vb_ = kb_ + 1024;
        __nv_bfloat16* ks = Ks + stage * STG_KV;
        __nv_bfloat16* vs = Vs + stage * STG_KV;
        #pragma unroll
        for (int p = 0; p < 2; p++) {
            int f = tid + p * 256;
            int r = f >> 3, c8 = (f & 7) * 8;
            cp16(&ks[r * FST + c8], kb_ + (size_t)r * 3072 + c8);
            cp16(&vs[r * FST + c8], vb_ + (size_t)r * 3072 + c8);
        }
    };

    load_kv(0, 0);
    {
        const __nv_bfloat16* qg = qkv + (size_t)tok0 * 3072 + h * 64;
        #pragma unroll
        for (int p = 0; p < 4; p++) {
            int f = tid + p * 256;
            int r = f >> 3, c8 = (f & 7) * 8;
            cp16(&Qs[r * FST + c8], qg + (size_t)r * 3072 + c8);
        }
    }
    asm volatile("cp.async.commit_group;");
    asm volatile("cp.async.wait_group 0;");
    __syncthreads();

    uint32_t qf[4][4];
    #pragma unroll
    for (int ks = 0; ks < 4; ks++)
        ldsm_x4(qf[ks][0], qf[ks][1], qf[ks][2], qf[ks][3],
                &Qs[(w * 16 + l15) * FST + ks * 16 + lhi]);

    float m0r = -1e30f, m1r = -1e30f, l0 = 0.f, l1 = 0.f;
    float of[8][4];
    #pragma unroll
    for (int nf = 0; nf < 8; nf++)
        #pragma unroll
        for (int j = 0; j < 4; j++) of[nf][j] = 0.f;

    const int qrow0 = qt * FQ + mrow;
    const int qrow1 = qrow0 + 8;

    for (int kt = 0; kt < nkt; kt++) {
        const int buf = kt & 1;
        asm volatile("cp.async.wait_group 0;");
        __syncthreads();   // K/V(kt) visible; PV(kt-1) done -> buf^1 free

        if (kt + 1 < nkt) load_kv(buf ^ 1, kt + 1);
        asm volatile("cp.async.commit_group;");

        const __nv_bfloat16* kcur = Ks + buf * STG_KV;
        const __nv_bfloat16* vcur = Vs + buf * STG_KV;

        float sc[8][4];
        #pragma unroll
        for (int nf = 0; nf < 8; nf++)
            #pragma unroll
            for (int j = 0; j < 4; j++) sc[nf][j] = 0.f;
        #pragma unroll
        for (int ks = 0; ks < 4; ks++) {
            const int kb = ks * 16;
            uint32_t bf[8][2];
            #pragma unroll
            for (int np = 0; np < 2; np++)
                #pragma unroll
                for (int pr = 0; pr < 2; pr++) {
                    uint32_t r0, r1, r2, r3;
                    ldsm_x4(r0, r1, r2, r3,
                            &kcur[(np * 32 + pr * 16 + lhi + l7) * FST
                                  + kb + selk * 8]);
                    bf[np * 4 + 2 * pr][0] = r0; bf[np * 4 + 2 * pr][1] = r1;
                    bf[np * 4 + 2 * pr + 1][0] = r2;
                    bf[np * 4 + 2 * pr + 1][1] = r3;
                }
            #pragma unroll
            for (int nf = 0; nf < 8; nf++)
                MMA_BF16(sc[nf], qf[ks], bf[nf]);
        }

        if (kt >= 2 * qt) {
            #pragma unroll
            for (int nf = 0; nf < 8; nf++) {
                int k0 = kt * FK + nf * 8 + 2 * t4;
                if (k0     > qrow0) sc[nf][0] = -1e30f;
                if (k0 + 1 > qrow0) sc[nf][1] = -1e30f;
                if (k0     > qrow1) sc[nf][2] = -1e30f;
                if (k0 + 1 > qrow1) sc[nf][3] = -1e30f;
            }
        }

        float mx0 = -1e30f, mx1 = -1e30f;
        #pragma unroll
        for (int nf = 0; nf < 8; nf++) {
            mx0 = fmaxf(mx0, fmaxf(sc[nf][0], sc[nf][1]));
            mx1 = fmaxf(mx1, fmaxf(sc[nf][2], sc[nf][3]));
        }
        mx0 = fmaxf(mx0, __shfl_xor_sync(0xffffffffu, mx0, 1));
        mx0 = fmaxf(mx0, __shfl_xor_sync(0xffffffffu, mx0, 2));
        mx1 = fmaxf(mx1, __shfl_xor_sync(0xffffffffu, mx1, 1));
        mx1 = fmaxf(mx1, __shfl_xor_sync(0xffffffffu, mx1, 2));
        float nm0 = fmaxf(m0r, mx0), nm1 = fmaxf(m1r, mx1);
        float fac0 = exp2f(m0r - nm0), fac1 = exp2f(m1r - nm1);
        m0r = nm0; m1r = nm1;

        uint32_t paf[8][2];
        float rs0 = 0.f, rs1 = 0.f;
        #pragma unroll
        for (int nf = 0; nf < 8; nf++) {
            float p00 = exp2f(sc[nf][0] - nm0);
            float p01 = exp2f(sc[nf][1] - nm0);
            float p10 = exp2f(sc[nf][2] - nm1);
            float p11 = exp2f(sc[nf][3] - nm1);
            rs0 += p00 + p01;
            rs1 += p10 + p11;
            paf[nf][0] = f2_to_bf16x2(p00, p01);
            paf[nf][1] = f2_to_bf16x2(p10, p11);
        }
        rs0 += __shfl_xor_sync(0xffffffffu, rs0, 1);
        rs0 += __shfl_xor_sync(0xffffffffu, rs0, 2);
        rs1 += __shfl_xor_sync(0xffffffffu, rs1, 1);
        rs1 += __shfl_xor_sync(0xffffffffu, rs1, 2);
        l0 = l0 * fac0 + rs0;
        l1 = l1 * fac1 + rs1;
        #pragma unroll
        for (int nf = 0; nf < 8; nf++) {
            of[nf][0] *= fac0; of[nf][1] *= fac0;
            of[nf][2] *= fac1; of[nf][3] *= fac1;
        }

        #pragma unroll
        for (int ks = 0; ks < 4; ks++) {
            const int kb = ks * 16;
            uint32_t af[4];
            af[0] = paf[2 * ks][0];
            af[1] = paf[2 * ks][1];
            af[2] = paf[2 * ks + 1][0];
            af[3] = paf[2 * ks + 1][1];
            uint32_t bf[8][2];
            #pragma unroll
            for (int ntp = 0; ntp < 4; ntp++) {
                uint32_t r0, r1, r2, r3;
                ldsm_x4_t(r0, r1, r2, r3,
                          &vcur[(kb + l15) * FST + ntp * 16 + lhi]);
                bf[2 * ntp][0] = r0;     bf[2 * ntp][1] = r1;
                bf[2 * ntp + 1][0] = r2; bf[2 * ntp + 1][1] = r3;
            }
            #pragma unroll
            for (int nf = 0; nf < 8; nf++)
                MMA_BF16(of[nf], af, bf[nf]);
        }
    }

    float inv0 = 1.0f / l0, inv1 = 1.0f / l1;
    int row0 = tok0 + mrow, row1 = row0 + 8;
    #pragma unroll
    for (int nf = 0; nf < 8; nf++) {
        int col = h * 64 + nf * 8 + 2 * t4;
        *(uint32_t*)&outp[(size_t)row0 * D_MODEL + col] =
            f2_to_bf16x2(of[nf][0] * inv0, of[nf][1] * inv0);
        *(uint32_t*)&outp[(size_t)row1 * D_MODEL + col] =
            f2_to_bf16x2(of[nf][2] * inv1, of[nf][3] * inv1);
    }
}

// ---------------- launcher ----------------
extern "C" void kernel_launch(void* const* d_in, const int* in_sizes, int n_in,
                              void* d_out, int out_size)
{
    const float* x      = (const float*)d_in[0];
    const float* qkv_w  = (const float*)d_in[1];
    const float* qkv_b  = (const float*)d_in[2];
    const float* out_w  = (const float*)d_in[3];
    const float* out_b  = (const float*)d_in[4];
    const float* ffn1_w = (const float*)d_in[5];
    const float* ffn1_b = (const float*)d_in[6];
    const float* ffn2_w = (const float*)d_in[7];
    const float* ffn2_b = (const float*)d_in[8];
    const float* ln1_g  = (const float*)d_in[9];
    const float* ln1_b  = (const float*)d_in[10];
    const float* ln2_g  = (const float*)d_in[11];
    const float* ln2_b  = (const float*)d_in[12];
    float* outp = (float*)d_out;

    float *x1;
    __nv_bfloat16 *qkvb, *nrm, *attn, *hb, *wq, *wo, *w1, *w2;
    cudaGetSymbolAddress((void**)&qkvb, g_qkv);
    cudaGetSymbolAddress((void**)&x1,   g_x1);
    cudaGetSymbolAddress((void**)&nrm,  g_nrm);
    cudaGetSymbolAddress((void**)&attn, g_attn);
    cudaGetSymbolAddress((void**)&hb,   g_h);
    cudaGetSymbolAddress((void**)&wq,   g_wq);
    cudaGetSymbolAddress((void**)&wo,   g_wo);
    cudaGetSymbolAddress((void**)&w1,   g_w1);
    cudaGetSymbolAddress((void**)&w2,   g_w2);

    cudaFuncSetAttribute(flash_tc,
                         cudaFuncAttributeMaxDynamicSharedMemorySize, FLASH_SMEM);
    cudaFuncSetAttribute(gemm_bf16<3,1>,
                         cudaFuncAttributeMaxDynamicSharedMemorySize, GEMM_SMEM);
    cudaFuncSetAttribute(gemm_bf16<1,1>,
                         cudaFuncAttributeMaxDynamicSharedMemorySize, GEMM_SMEM);
    cudaFuncSetAttribute(gemm_bf16<2,0>,
                         cudaFuncAttributeMaxDynamicSharedMemorySize, GEMM_SMEM);

    // 0+1) LN1 (warp-per-token) fused with weight convert (one launch)
    const int n0e = 3 * D_MODEL * D_MODEL / 4;
    const int n1e = D_MODEL * D_MODEL / 4;
    const int n2e = D_MODEL * DFF / 4;
    const int n3e = DFF * D_MODEL / 4;
    const int tot = n0e + n1e + n2e + n3e;
    const int cvt_blocks = (tot + 255) / 256;
    ln1_cvt_kernel<<<LN_BLOCKS + cvt_blocks, 256>>>(
        x, ln1_g, ln1_b, nrm,
        (const float4*)qkv_w,  (uint2*)wq, n0e,
        (const float4*)out_w,  (uint2*)wo, n1e,
        (const float4*)ffn1_w, (uint2*)w1, n2e,
        (const float4*)ffn2_w, (uint2*)w2, n3e);

    // 2) QKV projection -> bf16 qkvb (Q cols pre-scaled by 0.125*log2e)
    gemm_bf16<3,1><<<dim3(3 * D_MODEL / 128, NTOK / 128), 256, GEMM_SMEM>>>(
        nrm, wq, qkv_b, nullptr, qkvb, NTOK, 3 * D_MODEL, D_MODEL);
    // 3) flash attention (bf16, register-resident P) -> bf16 attn
    flash_tc<<<dim3(SEQ / FQ, NHEAD, BATCH), 256, FLASH_SMEM>>>(qkvb, attn);
    // 4) out projection + residual(x) -> fp32 x1
    gemm_bf16<2,0><<<dim3(D_MODEL / 128, NTOK / 128), 256, GEMM_SMEM>>>(
        attn, wo, out_b, x, x1, NTOK, D_MODEL, D_MODEL);
    // 5) LN2 -> bf16 (warp-per-token)
    ln_kernel<<<NTOK / 8, 256>>>(x1, ln2_g, ln2_b, nrm);
    // 6) FFN1 + GELU -> bf16 hb
    gemm_bf16<1,1><<<dim3(DFF / 128, NTOK / 128), 256, GEMM_SMEM>>>(
        nrm, w1, ffn1_b, nullptr, hb, NTOK, DFF, D_MODEL);
    // 7) FFN2 + residual(x1) -> fp32 out
    gemm_bf16<2,0><<<dim3(D_MODEL / 128, NTOK / 128), 256, GEMM_SMEM>>>(
        hb, w2, ffn2_b, x1, outp, NTOK, D_MODEL, DFF);
}

// round 16
// speedup vs baseline: 1.0032x; 1.0032x over previous
#include <cuda_runtime.h>
#include <cuda_bf16.h>
#include <math.h>
#include <stdint.h>

#define D_MODEL 1024
#define SEQ     2048
#define BATCH   4
#define NTOK    (BATCH*SEQ)      // 8192
#define NHEAD   16
#define HDIM    64
#define DFF     4096

// ---------------- scratch (alloc-free: __device__ globals) ----------------
__device__ __nv_bfloat16 g_qkv [(size_t)NTOK * 3 * D_MODEL];   // 48 MB bf16
__device__ float         g_x1  [(size_t)NTOK * D_MODEL];       // 32 MB fp32
__device__ __nv_bfloat16 g_nrm [(size_t)NTOK * D_MODEL];       // 16 MB
__device__ __nv_bfloat16 g_attn[(size_t)NTOK * D_MODEL];       // 16 MB
__device__ __nv_bfloat16 g_h   [(size_t)NTOK * DFF];           // 64 MB
__device__ __nv_bfloat16 g_wq  [(size_t)3 * D_MODEL * D_MODEL];
__device__ __nv_bfloat16 g_wo  [(size_t)D_MODEL * D_MODEL];
__device__ __nv_bfloat16 g_w1  [(size_t)D_MODEL * DFF];
__device__ __nv_bfloat16 g_w2  [(size_t)DFF * D_MODEL];

// ---------------- helpers ----------------
__device__ __forceinline__ float gelu_exact(float x) {
    return 0.5f * x * (1.0f + erff(x * 0.70710678118654752f));
}
__device__ __forceinline__ uint2 f4_to_bf16x4(float4 v) {
    __nv_bfloat162 lo = __floats2bfloat162_rn(v.x, v.y);
    __nv_bfloat162 hi = __floats2bfloat162_rn(v.z, v.w);
    uint2 r;
    r.x = *(uint32_t*)&lo;
    r.y = *(uint32_t*)&hi;
    return r;
}
__device__ __forceinline__ uint32_t f2_to_bf16x2(float a, float b) {
    __nv_bfloat162 p = __floats2bfloat162_rn(a, b);
    return *(uint32_t*)&p;
}
// packed bf16x2 exp2: one MUFU for two exps; output bits feed PV A-frags.
__device__ __forceinline__ uint32_t ex2_bf16x2(float a, float b) {
    uint32_t in = f2_to_bf16x2(a, b);
    uint32_t r;
    asm("ex2.approx.ftz.bf16x2 %0, %1;" : "=r"(r) : "r"(in));
    return r;
}
__device__ __forceinline__ float bf16lo_f32(uint32_t p) {
    return __uint_as_float(p << 16);
}
__device__ __forceinline__ float bf16hi_f32(uint32_t p) {
    return __uint_as_float(p & 0xffff0000u);
}
__device__ __forceinline__ void ldsm_x4(uint32_t& r0, uint32_t& r1,
                                        uint32_t& r2, uint32_t& r3,
                                        const void* p) {
    uint32_t a = (uint32_t)__cvta_generic_to_shared(p);
    asm volatile("ldmatrix.sync.aligned.m8n8.x4.shared.b16 {%0,%1,%2,%3}, [%4];"
                 : "=r"(r0), "=r"(r1), "=r"(r2), "=r"(r3) : "r"(a));
}
__device__ __forceinline__ void ldsm_x4_t(uint32_t& r0, uint32_t& r1,
                                          uint32_t& r2, uint32_t& r3,
                                          const void* p) {
    uint32_t a = (uint32_t)__cvta_generic_to_shared(p);
    asm volatile("ldmatrix.sync.aligned.m8n8.x4.trans.shared.b16 {%0,%1,%2,%3}, [%4];"
                 : "=r"(r0), "=r"(r1), "=r"(r2), "=r"(r3) : "r"(a));
}
__device__ __forceinline__ void cp16(void* dst, const void* src) {
    uint32_t d = (uint32_t)__cvta_generic_to_shared(dst);
    asm volatile("cp.async.cg.shared.global [%0], [%1], 16;" :: "r"(d), "l"(src));
}
#define MMA_BF16(accv, afv, bfv)                                            \
    asm volatile(                                                           \
        "mma.sync.aligned.m16n8k16.row.col.f32.bf16.bf16.f32 "              \
        "{%0,%1,%2,%3}, {%4,%5,%6,%7}, {%8,%9}, {%0,%1,%2,%3};"             \
        : "+f"((accv)[0]), "+f"((accv)[1]), "+f"((accv)[2]), "+f"((accv)[3])\
        : "r"((afv)[0]), "r"((afv)[1]), "r"((afv)[2]), "r"((afv)[3]),       \
          "r"((bfv)[0]), "r"((bfv)[1]))

// Q pre-scale folds 1/sqrt(64) AND log2(e): softmax computed base-2.
#define QSCALE (0.125f * 1.44269504088896340736f)

// ---------------- LayerNorm core: warp-per-token, shuffle-only --------------
__device__ __forceinline__ void ln_token(
    const float* __restrict__ x, const float* __restrict__ g,
    const float* __restrict__ b, __nv_bfloat16* __restrict__ y,
    int tok, int lane)
{
    const float4* row = (const float4*)(x + (size_t)tok * D_MODEL);
    float4 v[8];
    float s = 0.f, sq = 0.f;
    #pragma unroll
    for (int p = 0; p < 8; p++) {
        v[p] = row[p * 32 + lane];
        s  += v[p].x + v[p].y + v[p].z + v[p].w;
        sq += v[p].x*v[p].x + v[p].y*v[p].y + v[p].z*v[p].z + v[p].w*v[p].w;
    }
    #pragma unroll
    for (int o = 16; o > 0; o >>= 1) {
        s  += __shfl_xor_sync(0xffffffffu, s,  o);
        sq += __shfl_xor_sync(0xffffffffu, sq, o);
    }
    float mean = s * (1.0f / D_MODEL);
    float var  = sq * (1.0f / D_MODEL) - mean * mean;
    float rstd = rsqrtf(var + 1e-5f);
    uint2* yo = (uint2*)(y + (size_t)tok * D_MODEL);
    #pragma unroll
    for (int p = 0; p < 8; p++) {
        float4 gg = ((const float4*)g)[p * 32 + lane];
        float4 bb = ((const float4*)b)[p * 32 + lane];
        float4 o4;
        o4.x = (v[p].x - mean) * rstd * gg.x + bb.x;
        o4.y = (v[p].y - mean) * rstd * gg.y + bb.y;
        o4.z = (v[p].z - mean) * rstd * gg.z + bb.z;
        o4.w = (v[p].w - mean) * rstd * gg.w + bb.w;
        yo[p * 32 + lane] = f4_to_bf16x4(o4);
    }
}

// LN standalone (LN2): 8 tokens per block, 1024 blocks.
__global__ void __launch_bounds__(256) ln_kernel(
    const float* __restrict__ x, const float* __restrict__ g,
    const float* __restrict__ b, __nv_bfloat16* __restrict__ y)
{
    int tok = blockIdx.x * 8 + (threadIdx.x >> 5);
    ln_token(x, g, b, y, tok, threadIdx.x & 31);
}

// LN1 fused with weight convert.
#define LN_BLOCKS (NTOK / 8)
__global__ void __launch_bounds__(256) ln1_cvt_kernel(
    const float* __restrict__ x, const float* __restrict__ g,
    const float* __restrict__ b, __nv_bfloat16* __restrict__ y,
    const float4* __restrict__ s0, uint2* __restrict__ d0, int n0e,
    const float4* __restrict__ s1, uint2* __restrict__ d1, int n1e,
    const float4* __restrict__ s2, uint2* __restrict__ d2, int n2e,
    const float4* __restrict__ s3, uint2* __restrict__ d3, int n3e)
{
    if (blockIdx.x < LN_BLOCKS) {
        int tok = blockIdx.x * 8 + (threadIdx.x >> 5);
        ln_token(x, g, b, y, tok, threadIdx.x & 31);
        return;
    }
    int i = (blockIdx.x - LN_BLOCKS) * 256 + threadIdx.x;
    const float4* src; uint2* dst; int n;
    if (i < n0e)                      { src = s0; dst = d0; n = i; }
    else if ((i -= n0e) < n1e)        { src = s1; dst = d1; n = i; }
    else if ((i -= n1e) < n2e)        { src = s2; dst = d2; n = i; }
    else if ((i -= n2e) < n3e)        { src = s3; dst = d3; n = i; }
    else return;
    dst[n] = f4_to_bf16x4(src[n]);
}

// ---------------- bf16 GEMM: EXACT R6 configuration --------------------------
#define ASTR 40
#define BSTR 136
#define GSTAGE 3
#define GEMM_SMEM (GSTAGE * (128 * ASTR + 32 * BSTR) * 2)   // 56832 B

template<int EPI, int OUTBF>
__global__ void __launch_bounds__(256, 2) gemm_bf16(
    const __nv_bfloat16* __restrict__ A, const __nv_bfloat16* __restrict__ B,
    const float* __restrict__ bias, const float* __restrict__ Rsd,
    void* __restrict__ Cout, int M, int N, int K)
{
    extern __shared__ __nv_bfloat16 dynsm[];
    __nv_bfloat16* Asm = dynsm;
    __nv_bfloat16* Bsm = dynsm + GSTAGE * 128 * ASTR;

    const int tid  = threadIdx.x;
    const int lane = tid & 31, warp = tid >> 5;
    const int wm = warp >> 2, wn = warp & 3;
    const int g  = lane >> 2, t4 = lane & 3;
    const int l15 = lane & 15, lhi = (lane >> 4) << 3;
    const int m0 = blockIdx.y * 128, n0 = blockIdx.x * 128;

    float acc[4][4][4];
    #pragma unroll
    for (int i = 0; i < 4; i++)
        #pragma unroll
        for (int j = 0; j < 4; j++)
            #pragma unroll
            for (int r = 0; r < 4; r++) acc[i][j][r] = 0.f;

    const int ar = tid >> 2,  ac8 = (tid & 3) * 8;
    const int br = tid >> 4,  bc8 = (tid & 15) * 8;
    const __nv_bfloat16* Abase = A + (size_t)(m0 + ar) * K + ac8;
    const __nv_bfloat16* Bbase = B + n0 + bc8;

    auto load_stage = [&](int s, int k0) {
        __nv_bfloat16* as = Asm + s * 128 * ASTR;
        __nv_bfloat16* bs = Bsm + s * 32 * BSTR;
        cp16(&as[(ar     ) * ASTR + ac8], Abase + k0);
        cp16(&as[(ar + 64) * ASTR + ac8], Abase + (size_t)64 * K + k0);
        cp16(&bs[(br     ) * BSTR + bc8], Bbase + (size_t)(k0 + br) * N);
        cp16(&bs[(br + 16) * BSTR + bc8], Bbase + (size_t)(k0 + br + 16) * N);
    };

    load_stage(0, 0);
    asm volatile("cp.async.commit_group;");
    load_stage(1, 32);
    asm volatile("cp.async.commit_group;");

    int buf = 0;
    for (int k0 = 0; k0 < K; k0 += 32) {
        asm volatile("cp.async.wait_group 1;");
        __syncthreads();

        const __nv_bfloat16* a  = Asm + buf * 128 * ASTR;
        const __nv_bfloat16* bs = Bsm + buf * 32 * BSTR;
        #pragma unroll
        for (int ks = 0; ks < 2; ks++) {
            const int kb = ks * 16;
            uint32_t af[4][4];
            #pragma unroll
            for (int mt = 0; mt < 4; mt++)
                ldsm_x4(af[mt][0], af[mt][1], af[mt][2], af[mt][3],
                        &a[(wm * 64 + mt * 16 + l15) * ASTR + kb + lhi]);
            uint32_t bf_[4][2];
            #pragma unroll
            for (int ntp = 0; ntp < 2; ntp++) {
                uint32_t r0, r1, r2, r3;
                ldsm_x4_t(r0, r1, r2, r3,
                          &bs[(kb + l15) * BSTR + wn * 32 + ntp * 16 + lhi]);
                bf_[2 * ntp][0] = r0;     bf_[2 * ntp][1] = r1;
                bf_[2 * ntp + 1][0] = r2; bf_[2 * ntp + 1][1] = r3;
            }
            #pragma unroll
            for (int mt = 0; mt < 4; mt++)
                #pragma unroll
                for (int nt = 0; nt < 4; nt++)
                    MMA_BF16(acc[mt][nt], af[mt], bf_[nt]);
        }

        if (k0 + 64 < K) {
            int s = buf + 2; if (s >= GSTAGE) s -= GSTAGE;
            load_stage(s, k0 + 64);
        }
        asm volatile("cp.async.commit_group;");
        buf = (buf + 1 == GSTAGE) ? 0 : buf + 1;
    }

    #pragma unroll
    for (int mt = 0; mt < 4; mt++) {
        #pragma unroll
        for (int nt = 0; nt < 4; nt++) {
            int row = m0 + wm * 64 + mt * 16 + g;
            int col = n0 + wn * 32 + nt * 8 + t4 * 2;
            float2 bb = *(const float2*)(bias + col);
            #pragma unroll
            for (int h = 0; h < 2; h++) {
                int r = row + h * 8;
                float2 v;
                v.x = acc[mt][nt][h * 2 + 0] + bb.x;
                v.y = acc[mt][nt][h * 2 + 1] + bb.y;
                if (EPI == 1) { v.x = gelu_exact(v.x); v.y = gelu_exact(v.y); }
                if (EPI == 2) {
                    float2 rr = *(const float2*)(Rsd + (size_t)r * N + col);
                    v.x += rr.x; v.y += rr.y;
                }
                if (EPI == 3 && col < 1024) { v.x *= QSCALE; v.y *= QSCALE; }
                if (OUTBF) {
                    __nv_bfloat16* C = (__nv_bfloat16*)Cout;
                    *(uint32_t*)&C[(size_t)r * N + col] = f2_to_bf16x2(v.x, v.y);
                } else {
                    float* C = (float*)Cout;
                    *(float2*)(C + (size_t)r * N + col) = v;
                }
            }
        }
    }
}

// ---------------- Flash attention v5: register P + packed bf16x2 ex2 --------
#define FQ   128
#define FK   64
#define FST  72
#define STG_KV (FK * FST)
#define FLASH_SMEM ((FQ * FST + 4 * STG_KV) * 2)   // 55296 B

__global__ void __launch_bounds__(256, 2) flash_tc(
    const __nv_bfloat16* __restrict__ qkv, __nv_bfloat16* __restrict__ outp)
{
    extern __shared__ __nv_bfloat16 smb[];
    __nv_bfloat16* Qs = smb;                    // Q staging [128][FST]
    __nv_bfloat16* Ks = smb + FQ * FST;         // 2 x [64][FST]
    __nv_bfloat16* Vs = Ks + 2 * STG_KV;        // 2 x [64][FST]

    const int tid  = threadIdx.x;
    const int lane = tid & 31, w = tid >> 5;
    const int g = lane >> 2, t4 = lane & 3;
    const int l15 = lane & 15, l7 = lane & 7;
    const int lhi = (lane >> 4) << 3, selk = (lane >> 3) & 1;
    const int qt = (SEQ / FQ - 1) - blockIdx.x;   // heavy tiles first
    const int h  = blockIdx.y, b = blockIdx.z;
    const int tok0 = b * SEQ + qt * FQ;
    const int mrow = w * 16 + g;
    const int nkt = 2 * qt + 2;

    auto load_kv = [&](int stage, int kt2) {
        const __nv_bfloat16* kb_ =
            qkv + (size_t)(b * SEQ + kt2 * FK) * 3072 + 1024 + h * 64;
        const __nv_bfloat16* vb_ = kb_ + 1024;
        __nv_bfloat16* ks = Ks + stage * STG_KV;
        __nv_bfloat16* vs = Vs + stage * STG_KV;
        #pragma unroll
        for (int p = 0; p < 2; p++) {
            int f = tid + p * 256;
            int r = f >> 3, c8 = (f & 7) * 8;
            cp16(&ks[r * FST + c8], kb_ + (size_t)r * 3072 + c8);
            cp16(&vs[r * FST + c8], vb_ + (size_t)r * 3072 + c8);
        }
    };

    load_kv(0, 0);
    {
        const __nv_bfloat16* qg = qkv + (size_t)tok0 * 3072 + h * 64;
        #pragma unroll
        for (int p = 0; p < 4; p++) {
            int f = tid + p * 256;
            int r = f >> 3, c8 = (f & 7) * 8;
            cp16(&Qs[r * FST + c8], qg + (size_t)r * 3072 + c8);
        }
    }
    asm volatile("cp.async.commit_group;");
    asm volatile("cp.async.wait_group 0;");
    __syncthreads();

    uint32_t qf[4][4];
    #pragma unroll
    for (int ks = 0; ks < 4; ks++)
        ldsm_x4(qf[ks][0], qf[ks][1], qf[ks][2], qf[ks][3],
                &Qs[(w * 16 + l15) * FST + ks * 16 + lhi]);

    float m0r = -1e30f, m1r = -1e30f, l0 = 0.f, l1 = 0.f;
    float of[8][4];
    #pragma unroll
    for (int nf = 0; nf < 8; nf++)
        #pragma unroll
        for (int j = 0; j < 4; j++) of[nf][j] = 0.f;

    const int qrow0 = qt * FQ + mrow;
    const int qrow1 = qrow0 + 8;

    for (int kt = 0; kt < nkt; kt++) {
        const int buf = kt & 1;
        asm volatile("cp.async.wait_group 0;");
        __syncthreads();   // K/V(kt) visible; PV(kt-1) done -> buf^1 free

        if (kt + 1 < nkt) load_kv(buf ^ 1, kt + 1);
        asm volatile("cp.async.commit_group;");

        const __nv_bfloat16* kcur = Ks + buf * STG_KV;
        const __nv_bfloat16* vcur = Vs + buf * STG_KV;

        float sc[8][4];
        #pragma unroll
        for (int nf = 0; nf < 8; nf++)
            #pragma unroll
            for (int j = 0; j < 4; j++) sc[nf][j] = 0.f;
        #pragma unroll
        for (int ks = 0; ks < 4; ks++) {
            const int kb = ks * 16;
            uint32_t bf[8][2];
            #pragma unroll
            for (int np = 0; np < 2; np++)
                #pragma unroll
                for (int pr = 0; pr < 2; pr++) {
                    uint32_t r0, r1, r2, r3;
                    ldsm_x4(r0, r1, r2, r3,
                            &kcur[(np * 32 + pr * 16 + lhi + l7) * FST
                                  + kb + selk * 8]);
                    bf[np * 4 + 2 * pr][0] = r0; bf[np * 4 + 2 * pr][1] = r1;
                    bf[np * 4 + 2 * pr + 1][0] = r2;
                    bf[np * 4 + 2 * pr + 1][1] = r3;
                }
            #pragma unroll
            for (int nf = 0; nf < 8; nf++)
                MMA_BF16(sc[nf], qf[ks], bf[nf]);
        }

        if (kt >= 2 * qt) {
            #pragma unroll
            for (int nf = 0; nf < 8; nf++) {
                int k0 = kt * FK + nf * 8 + 2 * t4;
                if (k0     > qrow0) sc[nf][0] = -1e30f;
                if (k0 + 1 > qrow0) sc[nf][1] = -1e30f;
                if (k0     > qrow1) sc[nf][2] = -1e30f;
                if (k0 + 1 > qrow1) sc[nf][3] = -1e30f;
            }
        }

        float mx0 = -1e30f, mx1 = -1e30f;
        #pragma unroll
        for (int nf = 0; nf < 8; nf++) {
            mx0 = fmaxf(mx0, fmaxf(sc[nf][0], sc[nf][1]));
            mx1 = fmaxf(mx1, fmaxf(sc[nf][2], sc[nf][3]));
        }
        mx0 = fmaxf(mx0, __shfl_xor_sync(0xffffffffu, mx0, 1));
        mx0 = fmaxf(mx0, __shfl_xor_sync(0xffffffffu, mx0, 2));
        mx1 = fmaxf(mx1, __shfl_xor_sync(0xffffffffu, mx1, 1));
        mx1 = fmaxf(mx1, __shfl_xor_sync(0xffffffffu, mx1, 2));
        float nm0 = fmaxf(m0r, mx0), nm1 = fmaxf(m1r, mx1);
        float fac0 = exp2f(m0r - nm0), fac1 = exp2f(m1r - nm1);
        m0r = nm0; m1r = nm1;

        // packed bf16x2 exp2: output bits ARE the PV A-fragments; rs sums the
        // SAME rounded values (numerator/denominator exactly consistent).
        uint32_t paf[8][2];
        float rs0 = 0.f, rs1 = 0.f;
        #pragma unroll
        for (int nf = 0; nf < 8; nf++) {
            uint32_t p0 = ex2_bf16x2(sc[nf][0] - nm0, sc[nf][1] - nm0);
            uint32_t p1 = ex2_bf16x2(sc[nf][2] - nm1, sc[nf][3] - nm1);
            paf[nf][0] = p0;
            paf[nf][1] = p1;
            rs0 += bf16lo_f32(p0) + bf16hi_f32(p0);
            rs1 += bf16lo_f32(p1) + bf16hi_f32(p1);
        }
        rs0 += __shfl_xor_sync(0xffffffffu, rs0, 1);
        rs0 += __shfl_xor_sync(0xffffffffu, rs0, 2);
        rs1 += __shfl_xor_sync(0xffffffffu, rs1, 1);
        rs1 += __shfl_xor_sync(0xffffffffu, rs1, 2);
        l0 = l0 * fac0 + rs0;
        l1 = l1 * fac1 + rs1;
        #pragma unroll
        for (int nf = 0; nf < 8; nf++) {
            of[nf][0] *= fac0; of[nf][1] *= fac0;
            of[nf][2] *= fac1; of[nf][3] *= fac1;
        }

        #pragma unroll
        for (int ks = 0; ks < 4; ks++) {
            const int kb = ks * 16;
            uint32_t af[4];
            af[0] = paf[2 * ks][0];
            af[1] = paf[2 * ks][1];
            af[2] = paf[2 * ks + 1][0];
            af[3] = paf[2 * ks + 1][1];
            uint32_t bf[8][2];
            #pragma unroll
            for (int ntp = 0; ntp < 4; ntp++) {
                uint32_t r0, r1, r2, r3;
                ldsm_x4_t(r0, r1, r2, r3,
                          &vcur[(kb + l15) * FST + ntp * 16 + lhi]);
                bf[2 * ntp][0] = r0;     bf[2 * ntp][1] = r1;
                bf[2 * ntp + 1][0] = r2; bf[2 * ntp + 1][1] = r3;
            }
            #pragma unroll
            for (int nf = 0; nf < 8; nf++)
                MMA_BF16(of[nf], af, bf[nf]);
        }
    }

    float inv0 = 1.0f / l0, inv1 = 1.0f / l1;
    int row0 = tok0 + mrow, row1 = row0 + 8;
    #pragma unroll
    for (int nf = 0; nf < 8; nf++) {
        int col = h * 64 + nf * 8 + 2 * t4;
        *(uint32_t*)&outp[(size_t)row0 * D_MODEL + col] =
            f2_to_bf16x2(of[nf][0] * inv0, of[nf][1] * inv0);
        *(uint32_t*)&outp[(size_t)row1 * D_MODEL + col] =
            f2_to_bf16x2(of[nf][2] * inv1, of[nf][3] * inv1);
    }
}

// ---------------- launcher ----------------
extern "C" void kernel_launch(void* const* d_in, const int* in_sizes, int n_in,
                              void* d_out, int out_size)
{
    const float* x      = (const float*)d_in[0];
    const float* qkv_w  = (const float*)d_in[1];
    const float* qkv_b  = (const float*)d_in[2];
    const float* out_w  = (const float*)d_in[3];
    const float* out_b  = (const float*)d_in[4];
    const float* ffn1_w = (const float*)d_in[5];
    const float* ffn1_b = (const float*)d_in[6];
    const float* ffn2_w = (const float*)d_in[7];
    const float* ffn2_b = (const float*)d_in[8];
    const float* ln1_g  = (const float*)d_in[9];
    const float* ln1_b  = (const float*)d_in[10];
    const float* ln2_g  = (const float*)d_in[11];
    const float* ln2_b  = (const float*)d_in[12];
    float* outp = (float*)d_out;

    float *x1;
    __nv_bfloat16 *qkvb, *nrm, *attn, *hb, *wq, *wo, *w1, *w2;
    cudaGetSymbolAddress((void**)&qkvb, g_qkv);
    cudaGetSymbolAddress((void**)&x1,   g_x1);
    cudaGetSymbolAddress((void**)&nrm,  g_nrm);
    cudaGetSymbolAddress((void**)&attn, g_attn);
    cudaGetSymbolAddress((void**)&hb,   g_h);
    cudaGetSymbolAddress((void**)&wq,   g_wq);
    cudaGetSymbolAddress((void**)&wo,   g_wo);
    cudaGetSymbolAddress((void**)&w1,   g_w1);
    cudaGetSymbolAddress((void**)&w2,   g_w2);

    cudaFuncSetAttribute(flash_tc,
                         cudaFuncAttributeMaxDynamicSharedMemorySize, FLASH_SMEM);
    cudaFuncSetAttribute(gemm_bf16<3,1>,
                         cudaFuncAttributeMaxDynamicSharedMemorySize, GEMM_SMEM);
    cudaFuncSetAttribute(gemm_bf16<1,1>,
                         cudaFuncAttributeMaxDynamicSharedMemorySize, GEMM_SMEM);
    cudaFuncSetAttribute(gemm_bf16<2,0>,
                         cudaFuncAttributeMaxDynamicSharedMemorySize, GEMM_SMEM);

    // 0+1) LN1 (warp-per-token) fused with weight convert (one launch)
    const int n0e = 3 * D_MODEL * D_MODEL / 4;
    const int n1e = D_MODEL * D_MODEL / 4;
    const int n2e = D_MODEL * DFF / 4;
    const int n3e = DFF * D_MODEL / 4;
    const int tot = n0e + n1e + n2e + n3e;
    const int cvt_blocks = (tot + 255) / 256;
    ln1_cvt_kernel<<<LN_BLOCKS + cvt_blocks, 256>>>(
        x, ln1_g, ln1_b, nrm,
        (const float4*)qkv_w,  (uint2*)wq, n0e,
        (const float4*)out_w,  (uint2*)wo, n1e,
        (const float4*)ffn1_w, (uint2*)w1, n2e,
        (const float4*)ffn2_w, (uint2*)w2, n3e);

    // 2) QKV projection -> bf16 qkvb (Q cols pre-scaled by 0.125*log2e)
    gemm_bf16<3,1><<<dim3(3 * D_MODEL / 128, NTOK / 128), 256, GEMM_SMEM>>>(
        nrm, wq, qkv_b, nullptr, qkvb, NTOK, 3 * D_MODEL, D_MODEL);
    // 3) flash attention (bf16, register P, packed ex2) -> bf16 attn
    flash_tc<<<dim3(SEQ / FQ, NHEAD, BATCH), 256, FLASH_SMEM>>>(qkvb, attn);
    // 4) out projection + residual(x) -> fp32 x1
    gemm_bf16<2,0><<<dim3(D_MODEL / 128, NTOK / 128), 256, GEMM_SMEM>>>(
        attn, wo, out_b, x, x1, NTOK, D_MODEL, D_MODEL);
    // 5) LN2 -> bf16 (warp-per-token)
    ln_kernel<<<NTOK / 8, 256>>>(x1, ln2_g, ln2_b, nrm);
    // 6) FFN1 + GELU -> bf16 hb
    gemm_bf16<1,1><<<dim3(DFF / 128, NTOK / 128), 256, GEMM_SMEM>>>(
        nrm, w1, ffn1_b, nullptr, hb, NTOK, DFF, D_MODEL);
    // 7) FFN2 + residual(x1) -> fp32 out
    gemm_bf16<2,0><<<dim3(D_MODEL / 128, NTOK / 128), 256, GEMM_SMEM>>>(
        hb, w2, ffn2_b, x1, outp, NTOK, D_MODEL, DFF);
}

// round 17
// speedup vs baseline: 1.0102x; 1.0069x over previous
#include <cuda_runtime.h>
#include <cuda_bf16.h>
#include <math.h>
#include <stdint.h>

#define D_MODEL 1024
#define SEQ     2048
#define BATCH   4
#define NTOK    (BATCH*SEQ)      // 8192
#define NHEAD   16
#define HDIM    64
#define DFF     4096

// ---------------- scratch (alloc-free: __device__ globals) ----------------
__device__ __nv_bfloat16 g_qkv [(size_t)NTOK * 3 * D_MODEL];   // 48 MB bf16
__device__ float         g_x1  [(size_t)NTOK * D_MODEL];       // 32 MB fp32
__device__ __nv_bfloat16 g_nrm [(size_t)NTOK * D_MODEL];       // 16 MB
__device__ __nv_bfloat16 g_attn[(size_t)NTOK * D_MODEL];       // 16 MB
__device__ __nv_bfloat16 g_h   [(size_t)NTOK * DFF];           // 64 MB
__device__ __nv_bfloat16 g_wq  [(size_t)3 * D_MODEL * D_MODEL];
__device__ __nv_bfloat16 g_wo  [(size_t)D_MODEL * D_MODEL];
__device__ __nv_bfloat16 g_w1  [(size_t)D_MODEL * DFF];
__device__ __nv_bfloat16 g_w2  [(size_t)DFF * D_MODEL];

// ---------------- helpers ----------------
__device__ __forceinline__ float gelu_exact(float x) {
    return 0.5f * x * (1.0f + erff(x * 0.70710678118654752f));
}
__device__ __forceinline__ uint2 f4_to_bf16x4(float4 v) {
    __nv_bfloat162 lo = __floats2bfloat162_rn(v.x, v.y);
    __nv_bfloat162 hi = __floats2bfloat162_rn(v.z, v.w);
    uint2 r;
    r.x = *(uint32_t*)&lo;
    r.y = *(uint32_t*)&hi;
    return r;
}
__device__ __forceinline__ uint32_t f2_to_bf16x2(float a, float b) {
    __nv_bfloat162 p = __floats2bfloat162_rn(a, b);
    return *(uint32_t*)&p;
}
// packed bf16x2 exp2: one MUFU for two exps; output bits feed PV A-frags.
__device__ __forceinline__ uint32_t ex2_bf16x2(float a, float b) {
    uint32_t in = f2_to_bf16x2(a, b);
    uint32_t r;
    asm("ex2.approx.ftz.bf16x2 %0, %1;" : "=r"(r) : "r"(in));
    return r;
}
__device__ __forceinline__ float bf16lo_f32(uint32_t p) {
    return __uint_as_float(p << 16);
}
__device__ __forceinline__ float bf16hi_f32(uint32_t p) {
    return __uint_as_float(p & 0xffff0000u);
}
__device__ __forceinline__ void ldsm_x4(uint32_t& r0, uint32_t& r1,
                                        uint32_t& r2, uint32_t& r3,
                                        const void* p) {
    uint32_t a = (uint32_t)__cvta_generic_to_shared(p);
    asm volatile("ldmatrix.sync.aligned.m8n8.x4.shared.b16 {%0,%1,%2,%3}, [%4];"
                 : "=r"(r0), "=r"(r1), "=r"(r2), "=r"(r3) : "r"(a));
}
__device__ __forceinline__ void ldsm_x4_t(uint32_t& r0, uint32_t& r1,
                                          uint32_t& r2, uint32_t& r3,
                                          const void* p) {
    uint32_t a = (uint32_t)__cvta_generic_to_shared(p);
    asm volatile("ldmatrix.sync.aligned.m8n8.x4.trans.shared.b16 {%0,%1,%2,%3}, [%4];"
                 : "=r"(r0), "=r"(r1), "=r"(r2), "=r"(r3) : "r"(a));
}
__device__ __forceinline__ void cp16(void* dst, const void* src) {
    uint32_t d = (uint32_t)__cvta_generic_to_shared(dst);
    asm volatile("cp.async.cg.shared.global [%0], [%1], 16;" :: "r"(d), "l"(src));
}
#define MMA_BF16(accv, afv, bfv)                                            \
    asm volatile(                                                           \
        "mma.sync.aligned.m16n8k16.row.col.f32.bf16.bf16.f32 "              \
        "{%0,%1,%2,%3}, {%4,%5,%6,%7}, {%8,%9}, {%0,%1,%2,%3};"             \
        : "+f"((accv)[0]), "+f"((accv)[1]), "+f"((accv)[2]), "+f"((accv)[3])\
        : "r"((afv)[0]), "r"((afv)[1]), "r"((afv)[2]), "r"((afv)[3]),       \
          "r"((bfv)[0]), "r"((bfv)[1]))

// Q pre-scale folds 1/sqrt(64) AND log2(e): softmax computed base-2.
#define QSCALE (0.125f * 1.44269504088896340736f)

// ---------------- LayerNorm core: warp-per-token, shuffle-only --------------
__device__ __forceinline__ void ln_token(
    const float* __restrict__ x, const float* __restrict__ g,
    const float* __restrict__ b, __nv_bfloat16* __restrict__ y,
    int tok, int lane)
{
    const float4* row = (const float4*)(x + (size_t)tok * D_MODEL);
    float4 v[8];
    float s = 0.f, sq = 0.f;
    #pragma unroll
    for (int p = 0; p < 8; p++) {
        v[p] = row[p * 32 + lane];
        s  += v[p].x + v[p].y + v[p].z + v[p].w;
        sq += v[p].x*v[p].x + v[p].y*v[p].y + v[p].z*v[p].z + v[p].w*v[p].w;
    }
    #pragma unroll
    for (int o = 16; o > 0; o >>= 1) {
        s  += __shfl_xor_sync(0xffffffffu, s,  o);
        sq += __shfl_xor_sync(0xffffffffu, sq, o);
    }
    float mean = s * (1.0f / D_MODEL);
    float var  = sq * (1.0f / D_MODEL) - mean * mean;
    float rstd = rsqrtf(var + 1e-5f);
    uint2* yo = (uint2*)(y + (size_t)tok * D_MODEL);
    #pragma unroll
    for (int p = 0; p < 8; p++) {
        float4 gg = ((const float4*)g)[p * 32 + lane];
        float4 bb = ((const float4*)b)[p * 32 + lane];
        float4 o4;
        o4.x = (v[p].x - mean) * rstd * gg.x + bb.x;
        o4.y = (v[p].y - mean) * rstd * gg.y + bb.y;
        o4.z = (v[p].z - mean) * rstd * gg.z + bb.z;
        o4.w = (v[p].w - mean) * rstd * gg.w + bb.w;
        yo[p * 32 + lane] = f4_to_bf16x4(o4);
    }
}

// LN standalone (LN2): 8 tokens per block, 1024 blocks.
__global__ void __launch_bounds__(256) ln_kernel(
    const float* __restrict__ x, const float* __restrict__ g,
    const float* __restrict__ b, __nv_bfloat16* __restrict__ y)
{
    int tok = blockIdx.x * 8 + (threadIdx.x >> 5);
    ln_token(x, g, b, y, tok, threadIdx.x & 31);
}

// LN1 fused with weight convert.
#define LN_BLOCKS (NTOK / 8)
__global__ void __launch_bounds__(256) ln1_cvt_kernel(
    const float* __restrict__ x, const float* __restrict__ g,
    const float* __restrict__ b, __nv_bfloat16* __restrict__ y,
    const float4* __restrict__ s0, uint2* __restrict__ d0, int n0e,
    const float4* __restrict__ s1, uint2* __restrict__ d1, int n1e,
    const float4* __restrict__ s2, uint2* __restrict__ d2, int n2e,
    const float4* __restrict__ s3, uint2* __restrict__ d3, int n3e)
{
    if (blockIdx.x < LN_BLOCKS) {
        int tok = blockIdx.x * 8 + (threadIdx.x >> 5);
        ln_token(x, g, b, y, tok, threadIdx.x & 31);
        return;
    }
    int i = (blockIdx.x - LN_BLOCKS) * 256 + threadIdx.x;
    const float4* src; uint2* dst; int n;
    if (i < n0e)                      { src = s0; dst = d0; n = i; }
    else if ((i -= n0e) < n1e)        { src = s1; dst = d1; n = i; }
    else if ((i -= n1e) < n2e)        { src = s2; dst = d2; n = i; }
    else if ((i -= n2e) < n3e)        { src = s3; dst = d3; n = i; }
    else return;
    dst[n] = f4_to_bf16x4(src[n]);
}

// ---------------- bf16 GEMM: BK=64, R6 layout/ordering, 3-stage --------------
// A smem [m][k] stride 72 (144B rows, LDSM conflict-free); B smem [k][n]
// stride 136 (trans-LDSM path, proven). wait_group 1, refill AFTER compute.
// Halves barrier count vs BK=32 (16 syncs for K=1024).
// EPI: 0 bias, 1 bias+gelu, 2 bias+residual, 3 bias + qscale (cols<1024)
#define ASTR 72
#define BSTR 136
#define GSTAGE 3
#define STAGE_ELEMS (128 * ASTR + 64 * BSTR)               // 17920 elems
#define GEMM_SMEM (GSTAGE * STAGE_ELEMS * 2)               // 107520 B

template<int EPI, int OUTBF>
__global__ void __launch_bounds__(256, 2) gemm_bf16(
    const __nv_bfloat16* __restrict__ A, const __nv_bfloat16* __restrict__ B,
    const float* __restrict__ bias, const float* __restrict__ Rsd,
    void* __restrict__ Cout, int M, int N, int K)
{
    extern __shared__ __nv_bfloat16 dynsm[];

    const int tid  = threadIdx.x;
    const int lane = tid & 31, warp = tid >> 5;
    const int wm = warp >> 2, wn = warp & 3;
    const int g  = lane >> 2, t4 = lane & 3;
    const int l15 = lane & 15, lhi = (lane >> 4) << 3;
    const int m0 = blockIdx.y * 128, n0 = blockIdx.x * 128;
    const int nchunk = K >> 6;

    float acc[4][4][4];
    #pragma unroll
    for (int i = 0; i < 4; i++)
        #pragma unroll
        for (int j = 0; j < 4; j++)
            #pragma unroll
            for (int r = 0; r < 4; r++) acc[i][j][r] = 0.f;

    // loaders: A 128 rows x 8 chunks(8 elems) = 1024 cp16 -> 4/thread
    //          B  64 rows x 16 chunks         = 1024 cp16 -> 4/thread
    const __nv_bfloat16* Abase = A + (size_t)m0 * K;
    const __nv_bfloat16* Bbase = B + n0;

    auto load_stage = [&](int s, int k0) {
        __nv_bfloat16* as = dynsm + s * STAGE_ELEMS;
        __nv_bfloat16* bs = as + 128 * ASTR;
        #pragma unroll
        for (int p = 0; p < 4; p++) {
            int id = tid + p * 256;
            int arow = id >> 3, ac8 = (id & 7) * 8;
            cp16(&as[arow * ASTR + ac8],
                 Abase + (size_t)arow * K + k0 + ac8);
            int brow = id >> 4, bc8 = (id & 15) * 8;
            cp16(&bs[brow * BSTR + bc8],
                 Bbase + (size_t)(k0 + brow) * N + bc8);
        }
    };

    load_stage(0, 0);
    asm volatile("cp.async.commit_group;");
    load_stage(1, 64);
    asm volatile("cp.async.commit_group;");

    int buf = 0;
    for (int i = 0; i < nchunk; i++) {
        asm volatile("cp.async.wait_group 1;");
        __syncthreads();

        const __nv_bfloat16* a  = dynsm + buf * STAGE_ELEMS;
        const __nv_bfloat16* bs = a + 128 * ASTR;
        #pragma unroll
        for (int ks = 0; ks < 4; ks++) {
            const int kb = ks * 16;
            uint32_t af[4][4];
            #pragma unroll
            for (int mt = 0; mt < 4; mt++)
                ldsm_x4(af[mt][0], af[mt][1], af[mt][2], af[mt][3],
                        &a[(wm * 64 + mt * 16 + l15) * ASTR + kb + lhi]);
            uint32_t bf_[4][2];
            #pragma unroll
            for (int ntp = 0; ntp < 2; ntp++) {
                uint32_t r0, r1, r2, r3;
                ldsm_x4_t(r0, r1, r2, r3,
                          &bs[(kb + l15) * BSTR + wn * 32 + ntp * 16 + lhi]);
                bf_[2 * ntp][0] = r0;     bf_[2 * ntp][1] = r1;
                bf_[2 * ntp + 1][0] = r2; bf_[2 * ntp + 1][1] = r3;
            }
            #pragma unroll
            for (int mt = 0; mt < 4; mt++)
                #pragma unroll
                for (int nt = 0; nt < 4; nt++)
                    MMA_BF16(acc[mt][nt], af[mt], bf_[nt]);
        }

        if (i + 2 < nchunk) {
            int s = buf + 2; if (s >= GSTAGE) s -= GSTAGE;
            load_stage(s, (i + 2) << 6);
        }
        asm volatile("cp.async.commit_group;");
        buf = (buf + 1 == GSTAGE) ? 0 : buf + 1;
    }

    #pragma unroll
    for (int mt = 0; mt < 4; mt++) {
        #pragma unroll
        for (int nt = 0; nt < 4; nt++) {
            int row = m0 + wm * 64 + mt * 16 + g;
            int col = n0 + wn * 32 + nt * 8 + t4 * 2;
            float2 bb = *(const float2*)(bias + col);
            #pragma unroll
            for (int h = 0; h < 2; h++) {
                int r = row + h * 8;
                float2 v;
                v.x = acc[mt][nt][h * 2 + 0] + bb.x;
                v.y = acc[mt][nt][h * 2 + 1] + bb.y;
                if (EPI == 1) { v.x = gelu_exact(v.x); v.y = gelu_exact(v.y); }
                if (EPI == 2) {
                    float2 rr = *(const float2*)(Rsd + (size_t)r * N + col);
                    v.x += rr.x; v.y += rr.y;
                }
                if (EPI == 3 && col < 1024) { v.x *= QSCALE; v.y *= QSCALE; }
                if (OUTBF) {
                    __nv_bfloat16* C = (__nv_bfloat16*)Cout;
                    *(uint32_t*)&C[(size_t)r * N + col] = f2_to_bf16x2(v.x, v.y);
                } else {
                    float* C = (float*)Cout;
                    *(float2*)(C + (size_t)r * N + col) = v;
                }
            }
        }
    }
}

// ---------------- Flash attention v5: register P + packed bf16x2 ex2 --------
#define FQ   128
#define FK   64
#define FST  72
#define STG_KV (FK * FST)
#define FLASH_SMEM ((FQ * FST + 4 * STG_KV) * 2)   // 55296 B

__global__ void __launch_bounds__(256, 2) flash_tc(
    const __nv_bfloat16* __restrict__ qkv, __nv_bfloat16* __restrict__ outp)
{
    extern __shared__ __nv_bfloat16 smb[];
    __nv_bfloat16* Qs = smb;                    // Q staging [128][FST]
    __nv_bfloat16* Ks = smb + FQ * FST;         // 2 x [64][FST]
    __nv_bfloat16* Vs = Ks + 2 * STG_KV;        // 2 x [64][FST]

    const int tid  = threadIdx.x;
    const int lane = tid & 31, w = tid >> 5;
    const int g = lane >> 2, t4 = lane & 3;
    const int l15 = lane & 15, l7 = lane & 7;
    const int lhi = (lane >> 4) << 3, selk = (lane >> 3) & 1;
    const int qt = (SEQ / FQ - 1) - blockIdx.x;   // heavy tiles first
    const int h  = blockIdx.y, b = blockIdx.z;
    const int tok0 = b * SEQ + qt * FQ;
    const int mrow = w * 16 + g;
    const int nkt = 2 * qt + 2;

    auto load_kv = [&](int stage, int kt2) {
        const __nv_bfloat16* kb_ =
            qkv + (size_t)(b * SEQ + kt2 * FK) * 3072 + 1024 + h * 64;
        const __nv_bfloat16* vb_ = kb_ + 1024;
        __nv_bfloat16* ks = Ks + stage * STG_KV;
        __nv_bfloat16* vs = Vs + stage * STG_KV;
        #pragma unroll
        for (int p = 0; p < 2; p++) {
            int f = tid + p * 256;
            int r = f >> 3, c8 = (f & 7) * 8;
            cp16(&ks[r * FST + c8], kb_ + (size_t)r * 3072 + c8);
            cp16(&vs[r * FST + c8], vb_ + (size_t)r * 3072 + c8);
        }
    };

    load_kv(0, 0);
    {
        const __nv_bfloat16* qg = qkv + (size_t)tok0 * 3072 + h * 64;
        #pragma unroll
        for (int p = 0; p < 4; p++) {
            int f = tid + p * 256;
            int r = f >> 3, c8 = (f & 7) * 8;
            cp16(&Qs[r * FST + c8], qg + (size_t)r * 3072 + c8);
        }
    }
    asm volatile("cp.async.commit_group;");
    asm volatile("cp.async.wait_group 0;");
    __syncthreads();

    uint32_t qf[4][4];
    #pragma unroll
    for (int ks = 0; ks < 4; ks++)
        ldsm_x4(qf[ks][0], qf[ks][1], qf[ks][2], qf[ks][3],
                &Qs[(w * 16 + l15) * FST + ks * 16 + lhi]);

    float m0r = -1e30f, m1r = -1e30f, l0 = 0.f, l1 = 0.f;
    float of[8][4];
    #pragma unroll
    for (int nf = 0; nf < 8; nf++)
        #pragma unroll
        for (int j = 0; j < 4; j++) of[nf][j] = 0.f;

    const int qrow0 = qt * FQ + mrow;
    const int qrow1 = qrow0 + 8;

    for (int kt = 0; kt < nkt; kt++) {
        const int buf = kt & 1;
        asm volatile("cp.async.wait_group 0;");
        __syncthreads();   // K/V(kt) visible; PV(kt-1) done -> buf^1 free

        if (kt + 1 < nkt) load_kv(buf ^ 1, kt + 1);
        asm volatile("cp.async.commit_group;");

        const __nv_bfloat16* kcur = Ks + buf * STG_KV;
        const __nv_bfloat16* vcur = Vs + buf * STG_KV;

        float sc[8][4];
        #pragma unroll
        for (int nf = 0; nf < 8; nf++)
            #pragma unroll
            for (int j = 0; j < 4; j++) sc[nf][j] = 0.f;
        #pragma unroll
        for (int ks = 0; ks < 4; ks++) {
            const int kb = ks * 16;
            uint32_t bf[8][2];
            #pragma unroll
            for (int np = 0; np < 2; np++)
                #pragma unroll
                for (int pr = 0; pr < 2; pr++) {
                    uint32_t r0, r1, r2, r3;
                    ldsm_x4(r0, r1, r2, r3,
                            &kcur[(np * 32 + pr * 16 + lhi + l7) * FST
                                  + kb + selk * 8]);
                    bf[np * 4 + 2 * pr][0] = r0; bf[np * 4 + 2 * pr][1] = r1;
                    bf[np * 4 + 2 * pr + 1][0] = r2;
                    bf[np * 4 + 2 * pr + 1][1] = r3;
                }
            #pragma unroll
            for (int nf = 0; nf < 8; nf++)
                MMA_BF16(sc[nf], qf[ks], bf[nf]);
        }

        if (kt >= 2 * qt) {
            #pragma unroll
            for (int nf = 0; nf < 8; nf++) {
                int k0 = kt * FK + nf * 8 + 2 * t4;
                if (k0     > qrow0) sc[nf][0] = -1e30f;
                if (k0 + 1 > qrow0) sc[nf][1] = -1e30f;
                if (k0     > qrow1) sc[nf][2] = -1e30f;
                if (k0 + 1 > qrow1) sc[nf][3] = -1e30f;
            }
        }

        float mx0 = -1e30f, mx1 = -1e30f;
        #pragma unroll
        for (int nf = 0; nf < 8; nf++) {
            mx0 = fmaxf(mx0, fmaxf(sc[nf][0], sc[nf][1]));
            mx1 = fmaxf(mx1, fmaxf(sc[nf][2], sc[nf][3]));
        }
        mx0 = fmaxf(mx0, __shfl_xor_sync(0xffffffffu, mx0, 1));
        mx0 = fmaxf(mx0, __shfl_xor_sync(0xffffffffu, mx0, 2));
        mx1 = fmaxf(mx1, __shfl_xor_sync(0xffffffffu, mx1, 1));
        mx1 = fmaxf(mx1, __shfl_xor_sync(0xffffffffu, mx1, 2));
        float nm0 = fmaxf(m0r, mx0), nm1 = fmaxf(m1r, mx1);
        float fac0 = exp2f(m0r - nm0), fac1 = exp2f(m1r - nm1);
        m0r = nm0; m1r = nm1;

        uint32_t paf[8][2];
        float rs0 = 0.f, rs1 = 0.f;
        #pragma unroll
        for (int nf = 0; nf < 8; nf++) {
            uint32_t p0 = ex2_bf16x2(sc[nf][0] - nm0, sc[nf][1] - nm0);
            uint32_t p1 = ex2_bf16x2(sc[nf][2] - nm1, sc[nf][3] - nm1);
            paf[nf][0] = p0;
            paf[nf][1] = p1;
            rs0 += bf16lo_f32(p0) + bf16hi_f32(p0);
            rs1 += bf16lo_f32(p1) + bf16hi_f32(p1);
        }
        rs0 += __shfl_xor_sync(0xffffffffu, rs0, 1);
        rs0 += __shfl_xor_sync(0xffffffffu, rs0, 2);
        rs1 += __shfl_xor_sync(0xffffffffu, rs1, 1);
        rs1 += __shfl_xor_sync(0xffffffffu, rs1, 2);
        l0 = l0 * fac0 + rs0;
        l1 = l1 * fac1 + rs1;
        #pragma unroll
        for (int nf = 0; nf < 8; nf++) {
            of[nf][0] *= fac0; of[nf][1] *= fac0;
            of[nf][2] *= fac1; of[nf][3] *= fac1;
        }

        #pragma unroll
        for (int ks = 0; ks < 4; ks++) {
            const int kb = ks * 16;
            uint32_t af[4];
            af[0] = paf[2 * ks][0];
            af[1] = paf[2 * ks][1];
            af[2] = paf[2 * ks + 1][0];
            af[3] = paf[2 * ks + 1][1];
            uint32_t bf[8][2];
            #pragma unroll
            for (int ntp = 0; ntp < 4; ntp++) {
                uint32_t r0, r1, r2, r3;
                ldsm_x4_t(r0, r1, r2, r3,
                          &vcur[(kb + l15) * FST + ntp * 16 + lhi]);
                bf[2 * ntp][0] = r0;     bf[2 * ntp][1] = r1;
                bf[2 * ntp + 1][0] = r2; bf[2 * ntp + 1][1] = r3;
            }
            #pragma unroll
            for (int nf = 0; nf < 8; nf++)
                MMA_BF16(of[nf], af, bf[nf]);
        }
    }

    float inv0 = 1.0f / l0, inv1 = 1.0f / l1;
    int row0 = tok0 + mrow, row1 = row0 + 8;
    #pragma unroll
    for (int nf = 0; nf < 8; nf++) {
        int col = h * 64 + nf * 8 + 2 * t4;
        *(uint32_t*)&outp[(size_t)row0 * D_MODEL + col] =
            f2_to_bf16x2(of[nf][0] * inv0, of[nf][1] * inv0);
        *(uint32_t*)&outp[(size_t)row1 * D_MODEL + col] =
            f2_to_bf16x2(of[nf][2] * inv1, of[nf][3] * inv1);
    }
}

// ---------------- launcher ----------------
extern "C" void kernel_launch(void* const* d_in, const int* in_sizes, int n_in,
                              void* d_out, int out_size)
{
    const float* x      = (const float*)d_in[0];
    const float* qkv_w  = (const float*)d_in[1];
    const float* qkv_b  = (const float*)d_in[2];
    const float* out_w  = (const float*)d_in[3];
    const float* out_b  = (const float*)d_in[4];
    const float* ffn1_w = (const float*)d_in[5];
    const float* ffn1_b = (const float*)d_in[6];
    const float* ffn2_w = (const float*)d_in[7];
    const float* ffn2_b = (const float*)d_in[8];
    const float* ln1_g  = (const float*)d_in[9];
    const float* ln1_b  = (const float*)d_in[10];
    const float* ln2_g  = (const float*)d_in[11];
    const float* ln2_b  = (const float*)d_in[12];
    float* outp = (float*)d_out;

    float *x1;
    __nv_bfloat16 *qkvb, *nrm, *attn, *hb, *wq, *wo, *w1, *w2;
    cudaGetSymbolAddress((void**)&qkvb, g_qkv);
    cudaGetSymbolAddress((void**)&x1,   g_x1);
    cudaGetSymbolAddress((void**)&nrm,  g_nrm);
    cudaGetSymbolAddress((void**)&attn, g_attn);
    cudaGetSymbolAddress((void**)&hb,   g_h);
    cudaGetSymbolAddress((void**)&wq,   g_wq);
    cudaGetSymbolAddress((void**)&wo,   g_wo);
    cudaGetSymbolAddress((void**)&w1,   g_w1);
    cudaGetSymbolAddress((void**)&w2,   g_w2);

    cudaFuncSetAttribute(flash_tc,
                         cudaFuncAttributeMaxDynamicSharedMemorySize, FLASH_SMEM);
    cudaFuncSetAttribute(gemm_bf16<3,1>,
                         cudaFuncAttributeMaxDynamicSharedMemorySize, GEMM_SMEM);
    cudaFuncSetAttribute(gemm_bf16<1,1>,
                         cudaFuncAttributeMaxDynamicSharedMemorySize, GEMM_SMEM);
    cudaFuncSetAttribute(gemm_bf16<2,0>,
                         cudaFuncAttributeMaxDynamicSharedMemorySize, GEMM_SMEM);

    // 0+1) LN1 (warp-per-token) fused with weight convert (one launch)
    const int n0e = 3 * D_MODEL * D_MODEL / 4;
    const int n1e = D_MODEL * D_MODEL / 4;
    const int n2e = D_MODEL * DFF / 4;
    const int n3e = DFF * D_MODEL / 4;
    const int tot = n0e + n1e + n2e + n3e;
    const int cvt_blocks = (tot + 255) / 256;
    ln1_cvt_kernel<<<LN_BLOCKS + cvt_blocks, 256>>>(
        x, ln1_g, ln1_b, nrm,
        (const float4*)qkv_w,  (uint2*)wq, n0e,
        (const float4*)out_w,  (uint2*)wo, n1e,
        (const float4*)ffn1_w, (uint2*)w1, n2e,
        (const float4*)ffn2_w, (uint2*)w2, n3e);

    // 2) QKV projection -> bf16 qkvb (Q cols pre-scaled by 0.125*log2e)
    gemm_bf16<3,1><<<dim3(3 * D_MODEL / 128, NTOK / 128), 256, GEMM_SMEM>>>(
        nrm, wq, qkv_b, nullptr, qkvb, NTOK, 3 * D_MODEL, D_MODEL);
    // 3) flash attention (bf16, register P, packed ex2) -> bf16 attn
    flash_tc<<<dim3(SEQ / FQ, NHEAD, BATCH), 256, FLASH_SMEM>>>(qkvb, attn);
    // 4) out projection + residual(x) -> fp32 x1
    gemm_bf16<2,0><<<dim3(D_MODEL / 128, NTOK / 128), 256, GEMM_SMEM>>>(
        attn, wo, out_b, x, x1, NTOK, D_MODEL, D_MODEL);
    // 5) LN2 -> bf16 (warp-per-token)
    ln_kernel<<<NTOK / 8, 256>>>(x1, ln2_g, ln2_b, nrm);
    // 6) FFN1 + GELU -> bf16 hb
    gemm_bf16<1,1><<<dim3(DFF / 128, NTOK / 128), 256, GEMM_SMEM>>>(
        nrm, w1, ffn1_b, nullptr, hb, NTOK, DFF, D_MODEL);
    // 7) FFN2 + residual(x1) -> fp32 out
    gemm_bf16<2,0><<<dim3(D_MODEL / 128, NTOK / 128), 256, GEMM_SMEM>>>(
        hb, w2, ffn2_b, x1, outp, NTOK, D_MODEL, DFF);
}